// round 5
// baseline (speedup 1.0000x reference)
#include <cuda_runtime.h>
#include <cuda_bf16.h>
#include <math.h>
#include <stdint.h>

// ---------------------------------------------------------------------------
// EEGformer forward. bf16x3 (hi/lo split) GEMMs via mma.sync m16n8k16 HMMA.
// Fused qkv+rsa+imv kernel; resident-A multi-N-chunk GEMM for init/wo/fc1.
// A=120, B=2048, Bp1=2049, M=128, T = 120*2049 = 245880 tokens.
// ---------------------------------------------------------------------------

#define AA    120
#define BB    2048
#define BP1   2049
#define TTOK  (AA * BP1)      // 245880
#define TXTOK (AA * BB)       // 245760

__device__ float g_z  [(size_t)TTOK * 128];   // z planes / imv planes (aliased)
__device__ float g_big[(size_t)TTOK * 512];   // x planes / imv32 / h planes
__device__ __nv_bfloat16 g_w_hi[278528];
__device__ __nv_bfloat16 g_w_lo[278528];

// ---------------------------------------------------------------------------
// PTX helpers (sm_80-era, valid on sm_100 base target)
// ---------------------------------------------------------------------------
__device__ __forceinline__ uint32_t smem_to_u32(const void* p) {
    uint32_t a;
    asm("{ .reg .u64 t; cvta.to.shared.u64 t, %1; cvt.u32.u64 %0, t; }" : "=r"(a) : "l"(p));
    return a;
}
__device__ __forceinline__ void ldm4(uint32_t r[4], uint32_t addr) {
    asm volatile("ldmatrix.sync.aligned.m8n8.x4.shared.b16 {%0,%1,%2,%3}, [%4];"
        : "=r"(r[0]), "=r"(r[1]), "=r"(r[2]), "=r"(r[3]) : "r"(addr));
}
__device__ __forceinline__ void mma16816(float d[4], const uint32_t a[4],
                                         uint32_t b0, uint32_t b1) {
    asm volatile("mma.sync.aligned.m16n8k16.row.col.f32.bf16.bf16.f32 "
        "{%0,%1,%2,%3}, {%4,%5,%6,%7}, {%8,%9}, {%0,%1,%2,%3};"
        : "+f"(d[0]), "+f"(d[1]), "+f"(d[2]), "+f"(d[3])
        : "r"(a[0]), "r"(a[1]), "r"(a[2]), "r"(a[3]), "r"(b0), "r"(b1));
}
__device__ __forceinline__ void cp16(uint32_t saddr, const void* g, bool p) {
    int sz = p ? 16 : 0;
    asm volatile("cp.async.cg.shared.global [%0], [%1], 16, %2;"
        :: "r"(saddr), "l"(g), "r"(sz) : "memory");
}
#define CP_COMMIT() asm volatile("cp.async.commit_group;" ::: "memory")
#define CP_WAIT1()  asm volatile("cp.async.wait_group 1;" ::: "memory")
#define CP_WAIT0()  asm volatile("cp.async.wait_group 0;" ::: "memory")

// Shared compute: one BK=32 K-tile of the 128x128 block, bf16x3 (3 MMAs/term).
// A tile at saA_hi/saA_lo, B tile at sbB (hi) / sbB+8192 (lo).
// acc[2][8][4]: warp tile 32(M, wid&3) x 64(N, wid>>2).
__device__ __forceinline__ void compute_tile(
    uint32_t saA_hi, uint32_t saA_lo, uint32_t sbB,
    int wid, int lane, float acc[2][8][4])
{
#pragma unroll
    for (int k16 = 0; k16 < 2; k16++) {
        uint32_t ahf[2][4], alf[2][4];
        {
            int r0 = (wid & 3) * 32 + (lane & 15);
            int kc = k16 * 2 + (lane >> 4);
#pragma unroll
            for (int mt = 0; mt < 2; mt++) {
                int r = r0 + mt * 16;
                uint32_t off = (uint32_t)r * 64 +
                               ((uint32_t)(kc ^ ((r >> 1) & 3)) << 4);
                ldm4(ahf[mt], saA_hi + off);
                ldm4(alf[mt], saA_lo + off);
            }
        }
#pragma unroll
        for (int j = 0; j < 4; j++) {
            int mi = lane >> 3;
            int nr = (wid >> 2) * 64 + j * 16 + (mi >> 1) * 8 + (lane & 7);
            int kcb = k16 * 2 + (mi & 1);
            uint32_t off = (uint32_t)nr * 64 +
                           ((uint32_t)(kcb ^ ((nr >> 1) & 3)) << 4);
            uint32_t bh[4], bl[4];
            ldm4(bh, sbB + off);
            ldm4(bl, sbB + 8192 + off);
#pragma unroll
            for (int mt = 0; mt < 2; mt++) {
                mma16816(acc[mt][2 * j],     ahf[mt], bh[0], bh[1]);
                mma16816(acc[mt][2 * j],     ahf[mt], bl[0], bl[1]);
                mma16816(acc[mt][2 * j],     alf[mt], bh[0], bh[1]);
                mma16816(acc[mt][2 * j + 1], ahf[mt], bh[2], bh[3]);
                mma16816(acc[mt][2 * j + 1], ahf[mt], bl[2], bl[3]);
                mma16816(acc[mt][2 * j + 1], alf[mt], bh[2], bh[3]);
            }
        }
    }
}

// ---------------------------------------------------------------------------
// Resident-A GEMM: K=128 staged fully in smem once; NCH N-chunks looped
// in-CTA with double-buffered B. out[orow, col] (+bias)(gelu)(+addend).
// smem: A_hi 32K | A_lo 32K | B 2x16K  = 96KB.
// ---------------------------------------------------------------------------
template<int NCH, int REMAP, int GELU_F, int OUT_PLANES>
__global__ __launch_bounds__(256, 2)
void mma_gemm_res(const __nv_bfloat16* __restrict__ a_hi,
                  const __nv_bfloat16* __restrict__ a_lo,
                  const __nv_bfloat16* __restrict__ w_hi,
                  const __nv_bfloat16* __restrict__ w_lo,
                  const float* __restrict__ biasv,
                  const float* __restrict__ addend,
                  float* __restrict__ outf,
                  __nv_bfloat16* __restrict__ out_hi,
                  __nv_bfloat16* __restrict__ out_lo,
                  int T)
{
    constexpr int K = 128;
    constexpr int Nfull = NCH * 128;
    extern __shared__ char smem[];
    const uint32_t sbase = smem_to_u32(smem);
    const uint32_t sA_hi = sbase, sA_lo = sbase + 32768, sB = sbase + 65536;
    const int tid = threadIdx.x;
    const int wid = tid >> 5, lane = tid & 31;
    const int t0 = blockIdx.x * 128;

    // A resident: 4 kt tiles x 2 planes
    for (int i = tid; i < 2048; i += 256) {
        int kt = i >> 9, idx = i & 511;
        int row = idx >> 2, kc = idx & 3;
        uint32_t soff = (uint32_t)kt * 8192 + (uint32_t)row * 64 +
                        ((uint32_t)(kc ^ ((row >> 1) & 3)) << 4);
        int t = t0 + row;
        bool p = t < T;
        size_t ga = (size_t)(p ? t : 0) * K + kt * 32 + kc * 8;
        cp16(sA_hi + soff, a_hi + ga, p);
        cp16(sA_lo + soff, a_lo + ga, p);
    }

    auto stageB = [&](int g) {   // g = c*4 + kt
        int c = g >> 2, kt = g & 3;
        uint32_t sb = sB + (uint32_t)(g & 1) * 16384;
        for (int i = tid; i < 512; i += 256) {
            int row = i >> 2, kc = i & 3;
            uint32_t soff = (uint32_t)row * 64 +
                            ((uint32_t)(kc ^ ((row >> 1) & 3)) << 4);
            size_t gb = (size_t)(c * 128 + row) * K + kt * 32 + kc * 8;
            cp16(sb + soff, w_hi + gb, true);
            cp16(sb + 8192 + soff, w_lo + gb, true);
        }
    };

    stageB(0);
    CP_COMMIT();

    constexpr int NST = NCH * 4;
    int g = 0;
#pragma unroll 1
    for (int c = 0; c < NCH; c++) {
        float acc[2][8][4];
#pragma unroll
        for (int i = 0; i < 2; i++)
#pragma unroll
            for (int j = 0; j < 8; j++)
#pragma unroll
                for (int q = 0; q < 4; q++) acc[i][j][q] = 0.0f;

#pragma unroll 1
        for (int kt = 0; kt < 4; kt++, g++) {
            if (g + 1 < NST) { stageB(g + 1); CP_COMMIT(); CP_WAIT1(); }
            else             { CP_WAIT0(); }
            __syncthreads();
            compute_tile(sA_hi + (uint32_t)kt * 8192, sA_lo + (uint32_t)kt * 8192,
                         sB + (uint32_t)(g & 1) * 16384, wid, lane, acc);
            __syncthreads();
        }

        // Epilogue for chunk c
        const int colbase = c * 128 + (wid >> 2) * 64 + (lane & 3) * 2;
#pragma unroll
        for (int mt = 0; mt < 2; mt++) {
#pragma unroll
            for (int h2 = 0; h2 < 2; h2++) {
                int t = t0 + (wid & 3) * 32 + mt * 16 + (lane >> 2) + h2 * 8;
                if (t >= T) continue;
                size_t orow = REMAP ? ((size_t)t + (size_t)((unsigned)t / 2048u) + 1)
                                    : (size_t)t;
#pragma unroll
                for (int nt = 0; nt < 8; nt++) {
                    int col = colbase + nt * 8;
                    float v0 = acc[mt][nt][h2 * 2 + 0];
                    float v1 = acc[mt][nt][h2 * 2 + 1];
                    if (biasv) {
                        float2 b2 = *(const float2*)(biasv + col);
                        v0 += b2.x; v1 += b2.y;
                    }
                    if (GELU_F) {
                        v0 = 0.5f * v0 * (1.0f + erff(v0 * 0.70710678118654752f));
                        v1 = 0.5f * v1 * (1.0f + erff(v1 * 0.70710678118654752f));
                    }
                    if (addend) {
                        float2 a2 = *(const float2*)(addend + orow * Nfull + col);
                        v0 += a2.x; v1 += a2.y;
                    }
                    if (OUT_PLANES) {
                        __nv_bfloat162 h = __floats2bfloat162_rn(v0, v1);
                        __nv_bfloat162 l = __floats2bfloat162_rn(
                            v0 - __bfloat162float(h.x), v1 - __bfloat162float(h.y));
                        *(uint32_t*)(out_hi + orow * Nfull + col) = *(uint32_t*)&h;
                        *(uint32_t*)(out_lo + orow * Nfull + col) = *(uint32_t*)&l;
                    } else {
                        *(float2*)(outf + orow * Nfull + col) = make_float2(v0, v1);
                    }
                }
            }
        }
    }
}

// ---------------------------------------------------------------------------
// Fused QKV + rsa + imv kernel. A = z planes (K=128, resident). 3 chunks
// (q, k, v) looped in-CTA; q parked in smem fp32; k epilogue reduces q.k per
// head via shared atomics; v epilogue writes imv32 = 0.25*rsa*v.
// smem: A 64K | B 2x16K | Q 128x132 f32 (66K) | RSA 128x8 f32 (4K) = ~166KB.
// ---------------------------------------------------------------------------
__global__ __launch_bounds__(256, 1)
void qkv_rsa_kernel(const __nv_bfloat16* __restrict__ a_hi,
                    const __nv_bfloat16* __restrict__ a_lo,
                    const __nv_bfloat16* __restrict__ w_hi,
                    const __nv_bfloat16* __restrict__ w_lo,
                    float* __restrict__ imv32, int T)
{
    constexpr int K = 128;
    extern __shared__ char smem[];
    const uint32_t sbase = smem_to_u32(smem);
    const uint32_t sA_hi = sbase, sA_lo = sbase + 32768, sB = sbase + 65536;
    float* Q   = (float*)(smem + 98304);     // stride 132 floats per row
    float* RSA = (float*)(smem + 165888);    // [128][8]
    const int tid = threadIdx.x;
    const int wid = tid >> 5, lane = tid & 31;
    const int t0 = blockIdx.x * 128;

    // zero RSA
    for (int i = tid; i < 1024; i += 256) RSA[i] = 0.0f;

    // A resident
    for (int i = tid; i < 2048; i += 256) {
        int kt = i >> 9, idx = i & 511;
        int row = idx >> 2, kc = idx & 3;
        uint32_t soff = (uint32_t)kt * 8192 + (uint32_t)row * 64 +
                        ((uint32_t)(kc ^ ((row >> 1) & 3)) << 4);
        int t = t0 + row;
        bool p = t < T;
        size_t ga = (size_t)(p ? t : 0) * K + kt * 32 + kc * 8;
        cp16(sA_hi + soff, a_hi + ga, p);
        cp16(sA_lo + soff, a_lo + ga, p);
    }

    auto stageB = [&](int g) {
        int c = g >> 2, kt = g & 3;
        uint32_t sb = sB + (uint32_t)(g & 1) * 16384;
        for (int i = tid; i < 512; i += 256) {
            int row = i >> 2, kc = i & 3;
            uint32_t soff = (uint32_t)row * 64 +
                            ((uint32_t)(kc ^ ((row >> 1) & 3)) << 4);
            size_t gb = (size_t)(c * 128 + row) * K + kt * 32 + kc * 8;
            cp16(sb + soff, w_hi + gb, true);
            cp16(sb + 8192 + soff, w_lo + gb, true);
        }
    };

    stageB(0);
    CP_COMMIT();

    int g = 0;
#pragma unroll 1
    for (int c = 0; c < 3; c++) {
        float acc[2][8][4];
#pragma unroll
        for (int i = 0; i < 2; i++)
#pragma unroll
            for (int j = 0; j < 8; j++)
#pragma unroll
                for (int q = 0; q < 4; q++) acc[i][j][q] = 0.0f;

#pragma unroll 1
        for (int kt = 0; kt < 4; kt++, g++) {
            if (g + 1 < 12) { stageB(g + 1); CP_COMMIT(); CP_WAIT1(); }
            else            { CP_WAIT0(); }
            __syncthreads();
            compute_tile(sA_hi + (uint32_t)kt * 8192, sA_lo + (uint32_t)kt * 8192,
                         sB + (uint32_t)(g & 1) * 16384, wid, lane, acc);
            __syncthreads();
        }

        const int colloc = (wid >> 2) * 64 + (lane & 3) * 2;  // 0..126 within row
        if (c == 0) {
            // park q in smem
#pragma unroll
            for (int mt = 0; mt < 2; mt++)
#pragma unroll
                for (int h2 = 0; h2 < 2; h2++) {
                    int row = (wid & 3) * 32 + mt * 16 + (lane >> 2) + h2 * 8;
#pragma unroll
                    for (int nt = 0; nt < 8; nt++) {
                        int col = colloc + nt * 8;
                        *(float2*)(Q + row * 132 + col) =
                            make_float2(acc[mt][nt][h2 * 2], acc[mt][nt][h2 * 2 + 1]);
                    }
                }
            __syncthreads();
        } else if (c == 1) {
            // rsa partials: dot(q, k) per (row, head)
#pragma unroll
            for (int mt = 0; mt < 2; mt++)
#pragma unroll
                for (int h2 = 0; h2 < 2; h2++) {
                    int row = (wid & 3) * 32 + mt * 16 + (lane >> 2) + h2 * 8;
                    float p[4] = {0.f, 0.f, 0.f, 0.f};
#pragma unroll
                    for (int nt = 0; nt < 8; nt++) {
                        int col = colloc + nt * 8;
                        float2 qv = *(float2*)(Q + row * 132 + col);
                        p[nt >> 1] += qv.x * acc[mt][nt][h2 * 2]
                                    + qv.y * acc[mt][nt][h2 * 2 + 1];
                    }
#pragma unroll
                    for (int hl = 0; hl < 4; hl++)
                        atomicAdd(&RSA[row * 8 + (wid >> 2) * 4 + hl], p[hl]);
                }
            __syncthreads();
        } else {
            // imv = 0.25 * rsa * v -> global fp32
#pragma unroll
            for (int mt = 0; mt < 2; mt++)
#pragma unroll
                for (int h2 = 0; h2 < 2; h2++) {
                    int row = (wid & 3) * 32 + mt * 16 + (lane >> 2) + h2 * 8;
                    int t = t0 + row;
                    if (t >= T) continue;
#pragma unroll
                    for (int nt = 0; nt < 8; nt++) {
                        int col = colloc + nt * 8;
                        float r = RSA[row * 8 + (wid >> 2) * 4 + (nt >> 1)] * 0.25f;
                        *(float2*)(imv32 + (size_t)t * 128 + col) =
                            make_float2(r * acc[mt][nt][h2 * 2],
                                        r * acc[mt][nt][h2 * 2 + 1]);
                    }
                }
        }
    }
}

// ---------------------------------------------------------------------------
// Streaming GEMM for fc2 (K=512): double-buffered A+B, BK=32. (R4 kernel.)
// ---------------------------------------------------------------------------
__global__ __launch_bounds__(256, 2)
void mma_gemm_stream(const __nv_bfloat16* __restrict__ a_hi,
                     const __nv_bfloat16* __restrict__ a_lo,
                     const __nv_bfloat16* __restrict__ w_hi,
                     const __nv_bfloat16* __restrict__ w_lo,
                     const float* __restrict__ biasv,
                     const float* __restrict__ addend,
                     float* __restrict__ outf,
                     int T, int K)
{
    extern __shared__ char smem[];
    const uint32_t sbase = smem_to_u32(smem);
    const int tid = threadIdx.x;
    const int wid = tid >> 5, lane = tid & 31;
    const int t0 = blockIdx.x * 128;

    float acc[2][8][4];
#pragma unroll
    for (int i = 0; i < 2; i++)
#pragma unroll
        for (int j = 0; j < 8; j++)
#pragma unroll
            for (int q = 0; q < 4; q++) acc[i][j][q] = 0.0f;

    const int KT = K >> 5;

    auto stage = [&](int sbuf, int k0) {
        uint32_t sb = sbase + sbuf * 32768;
#pragma unroll
        for (int h = 0; h < 2; h++) {
            int cidx = tid + h * 256;
            int row = cidx >> 2, kc = cidx & 3;
            uint32_t soff = (uint32_t)row * 64 +
                            ((uint32_t)(kc ^ ((row >> 1) & 3)) << 4);
            int t = t0 + row;
            bool p = t < T;
            size_t ga = (size_t)(p ? t : 0) * K + k0 + kc * 8;
            cp16(sb + 0     + soff, a_hi + ga, p);
            cp16(sb + 8192  + soff, a_lo + ga, p);
            size_t gb = (size_t)row * K + k0 + kc * 8;
            cp16(sb + 16384 + soff, w_hi + gb, true);
            cp16(sb + 24576 + soff, w_lo + gb, true);
        }
    };

    stage(0, 0);
    CP_COMMIT();

    for (int kt = 0; kt < KT; kt++) {
        if (kt + 1 < KT) { stage((kt + 1) & 1, (kt + 1) << 5); CP_COMMIT(); CP_WAIT1(); }
        else             { CP_WAIT0(); }
        __syncthreads();
        uint32_t sb = sbase + (kt & 1) * 32768;
        compute_tile(sb, sb + 8192, sb + 16384, wid, lane, acc);
        __syncthreads();
    }

    const int colbase = (wid >> 2) * 64 + (lane & 3) * 2;
#pragma unroll
    for (int mt = 0; mt < 2; mt++) {
#pragma unroll
        for (int h2 = 0; h2 < 2; h2++) {
            int t = t0 + (wid & 3) * 32 + mt * 16 + (lane >> 2) + h2 * 8;
            if (t >= T) continue;
#pragma unroll
            for (int nt = 0; nt < 8; nt++) {
                int col = colbase + nt * 8;
                float v0 = acc[mt][nt][h2 * 2 + 0];
                float v1 = acc[mt][nt][h2 * 2 + 1];
                if (biasv) {
                    float2 b2 = *(const float2*)(biasv + col);
                    v0 += b2.x; v1 += b2.y;
                }
                if (addend) {
                    float2 a2 = *(const float2*)(addend + (size_t)t * 128 + col);
                    v0 += a2.x; v1 += a2.y;
                }
                *(float2*)(outf + (size_t)t * 128 + col) = make_float2(v0, v1);
            }
        }
    }
}

// ---------------------------------------------------------------------------
// fp32 -> bf16 hi/lo split conversion.
// ---------------------------------------------------------------------------
__global__ void cvt4_kernel(const float4* __restrict__ src,
                            uint2* __restrict__ hi, uint2* __restrict__ lo, int n4)
{
    int i = blockIdx.x * blockDim.x + threadIdx.x;
    if (i >= n4) return;
    float4 v = src[i];
    __nv_bfloat162 h01 = __floats2bfloat162_rn(v.x, v.y);
    __nv_bfloat162 h23 = __floats2bfloat162_rn(v.z, v.w);
    __nv_bfloat162 l01 = __floats2bfloat162_rn(v.x - __bfloat162float(h01.x),
                                               v.y - __bfloat162float(h01.y));
    __nv_bfloat162 l23 = __floats2bfloat162_rn(v.z - __bfloat162float(h23.x),
                                               v.w - __bfloat162float(h23.y));
    hi[i] = make_uint2(*(uint32_t*)&h01, *(uint32_t*)&h23);
    lo[i] = make_uint2(*(uint32_t*)&l01, *(uint32_t*)&l23);
}

// ---------------------------------------------------------------------------
// LayerNorm (last dim 128) -> bf16 hi/lo planes.
// ---------------------------------------------------------------------------
__global__ void ln_kernel(const float* __restrict__ x,
                          const float* __restrict__ g,
                          const float* __restrict__ b,
                          __nv_bfloat16* __restrict__ z_hi,
                          __nv_bfloat16* __restrict__ z_lo, int T)
{
    int warp = threadIdx.x >> 5;
    int lane = threadIdx.x & 31;
    int t = blockIdx.x * 8 + warp;
    if (t >= T) return;

    float4 v = ((const float4*)(x + (size_t)t * 128))[lane];
    float s = v.x + v.y + v.z + v.w;
#pragma unroll
    for (int o = 16; o >= 1; o >>= 1) s += __shfl_xor_sync(0xffffffffu, s, o);
    float mu = s * (1.0f / 128.0f);
    float dx = v.x - mu, dy = v.y - mu, dz = v.z - mu, dw = v.w - mu;
    float q = dx * dx + dy * dy + dz * dz + dw * dw;
#pragma unroll
    for (int o = 16; o >= 1; o >>= 1) q += __shfl_xor_sync(0xffffffffu, q, o);
    float rs = rsqrtf(q * (1.0f / 128.0f) + 1e-5f);

    float4 gg = ((const float4*)g)[lane];
    float4 bb = ((const float4*)b)[lane];
    float o0 = dx * rs * gg.x + bb.x;
    float o1 = dy * rs * gg.y + bb.y;
    float o2 = dz * rs * gg.z + bb.z;
    float o3 = dw * rs * gg.w + bb.w;

    __nv_bfloat162 h01 = __floats2bfloat162_rn(o0, o1);
    __nv_bfloat162 h23 = __floats2bfloat162_rn(o2, o3);
    __nv_bfloat162 l01 = __floats2bfloat162_rn(o0 - __bfloat162float(h01.x),
                                               o1 - __bfloat162float(h01.y));
    __nv_bfloat162 l23 = __floats2bfloat162_rn(o2 - __bfloat162float(h23.x),
                                               o3 - __bfloat162float(h23.y));
    size_t base = (size_t)t * 128 + lane * 4;
    *(uint2*)(z_hi + base) = make_uint2(*(uint32_t*)&h01, *(uint32_t*)&h23);
    *(uint2*)(z_lo + base) = make_uint2(*(uint32_t*)&l01, *(uint32_t*)&l23);
}

// ---------------------------------------------------------------------------
// cumsum over j in [0,2048) per (i,f); row 2048 converted untouched.
// ---------------------------------------------------------------------------
__global__ void cumsum_kernel(const float* __restrict__ imv,
                              __nv_bfloat16* __restrict__ hi,
                              __nv_bfloat16* __restrict__ lo)
{
    int i = blockIdx.x;
    int f = threadIdx.x;
    size_t base = (size_t)i * BP1 * 128 + f;
    float acc = 0.0f;
    for (int j = 0; j < BB; j += 8) {
        float v[8];
#pragma unroll
        for (int u = 0; u < 8; u++) v[u] = imv[base + (size_t)(j + u) * 128];
#pragma unroll
        for (int u = 0; u < 8; u++) {
            acc += v[u];
            __nv_bfloat16 h = __float2bfloat16(acc);
            hi[base + (size_t)(j + u) * 128] = h;
            lo[base + (size_t)(j + u) * 128] = __float2bfloat16(acc - __bfloat162float(h));
        }
    }
    float v = imv[base + (size_t)BB * 128];
    __nv_bfloat16 h = __float2bfloat16(v);
    hi[base + (size_t)BB * 128] = h;
    lo[base + (size_t)BB * 128] = __float2bfloat16(v - __bfloat162float(h));
}

__global__ void cls_kernel(const float* __restrict__ cls,
                           const float* __restrict__ bias,
                           float* __restrict__ out)
{
    int i = blockIdx.x, l = threadIdx.x;
    out[(size_t)i * BP1 * 128 + l] = cls[i * 128 + l] + bias[(size_t)i * BP1 * 128 + l];
}

// ---------------------------------------------------------------------------
// Launch
// ---------------------------------------------------------------------------
extern "C" void kernel_launch(void* const* d_in, const int* in_sizes, int n_in,
                              void* d_out, int out_size)
{
    const float* x      = (const float*)d_in[0];
    const float* weight = (const float*)d_in[1];
    const float* cls    = (const float*)d_in[2];
    const float* bias   = (const float*)d_in[3];
    const float* Wqkv   = (const float*)d_in[4];
    const float* Wo     = (const float*)d_in[5];
    const float* ln1_g  = (const float*)d_in[6];
    const float* ln1_b  = (const float*)d_in[7];
    const float* ln2_g  = (const float*)d_in[8];
    const float* ln2_b  = (const float*)d_in[9];
    const float* fc1_w  = (const float*)d_in[10];
    const float* fc1_b  = (const float*)d_in[11];
    const float* fc2_w  = (const float*)d_in[12];
    const float* fc2_b  = (const float*)d_in[13];
    float* s = (float*)d_out;

    void *pz, *pbig, *pwh, *pwl;
    cudaGetSymbolAddress(&pz,   g_z);
    cudaGetSymbolAddress(&pbig, g_big);
    cudaGetSymbolAddress(&pwh,  g_w_hi);
    cudaGetSymbolAddress(&pwl,  g_w_lo);
    char* zb  = (char*)pz;
    char* big = (char*)pbig;
    __nv_bfloat16* w_hi = (__nv_bfloat16*)pwh;
    __nv_bfloat16* w_lo = (__nv_bfloat16*)pwl;

    const int T  = TTOK;
    const int Tx = TXTOK;
    const int tokBlocks = (T + 127) / 128;   // 1922
    const int txBlocks  = Tx / 128;          // 1920

    // scratch layouts
    __nv_bfloat16* z_hi   = (__nv_bfloat16*)zb;                 // T*128
    __nv_bfloat16* z_lo   = z_hi + (size_t)T * 128;
    __nv_bfloat16* imv_hi = z_hi;                               // alias (z dead)
    __nv_bfloat16* imv_lo = z_lo;
    float*         imv32  = (float*)big;                        // T*128 (front of big)
    __nv_bfloat16* h_hi   = (__nv_bfloat16*)big;                // T*512 (disjoint lifetime)
    __nv_bfloat16* h_lo   = h_hi + (size_t)T * 512;
    __nv_bfloat16* x_hi   = (__nv_bfloat16*)(big + (size_t)T * 128 * 4);  // after imv32
    __nv_bfloat16* x_lo   = x_hi + (size_t)Tx * 128;

    // weight plane offsets (elements)
    const int OFF_W    = 0;
    const int OFF_QKV  = 16384;
    const int OFF_WO   = 114688;
    const int OFF_FC1  = 147456;
    const int OFF_FC2  = 212992;

    const int SM_RES    = 98304;
    const int SM_QKV    = 169984;
    const int SM_STREAM = 65536;
    cudaFuncSetAttribute(mma_gemm_res<1,1,0,0>, cudaFuncAttributeMaxDynamicSharedMemorySize, SM_RES);
    cudaFuncSetAttribute(mma_gemm_res<1,0,0,0>, cudaFuncAttributeMaxDynamicSharedMemorySize, SM_RES);
    cudaFuncSetAttribute(mma_gemm_res<4,0,1,1>, cudaFuncAttributeMaxDynamicSharedMemorySize, SM_RES);
    cudaFuncSetAttribute(qkv_rsa_kernel, cudaFuncAttributeMaxDynamicSharedMemorySize, SM_QKV);
    cudaFuncSetAttribute(mma_gemm_stream, cudaFuncAttributeMaxDynamicSharedMemorySize, SM_STREAM);

    // --- weight + x conversions ---
    cvt4_kernel<<<(16384/4 + 255)/256, 256>>>((const float4*)weight,
        (uint2*)(w_hi + OFF_W), (uint2*)(w_lo + OFF_W), 16384/4);
    cvt4_kernel<<<(98304/4 + 255)/256, 256>>>((const float4*)Wqkv,
        (uint2*)(w_hi + OFF_QKV), (uint2*)(w_lo + OFF_QKV), 98304/4);
    cvt4_kernel<<<(32768/4 + 255)/256, 256>>>((const float4*)Wo,
        (uint2*)(w_hi + OFF_WO), (uint2*)(w_lo + OFF_WO), 32768/4);
    cvt4_kernel<<<(65536/4 + 255)/256, 256>>>((const float4*)fc1_w,
        (uint2*)(w_hi + OFF_FC1), (uint2*)(w_lo + OFF_FC1), 65536/4);
    cvt4_kernel<<<(65536/4 + 255)/256, 256>>>((const float4*)fc2_w,
        (uint2*)(w_hi + OFF_FC2), (uint2*)(w_lo + OFF_FC2), 65536/4);
    {
        int n4 = Tx * 128 / 4;
        cvt4_kernel<<<(n4 + 255)/256, 256>>>((const float4*)x, (uint2*)x_hi, (uint2*)x_lo, n4);
    }

    // s = concat([cls, x @ W^T], 1) + bias
    cls_kernel<<<AA, 128>>>(cls, bias, s);
    mma_gemm_res<1,1,0,0><<<txBlocks, 256, SM_RES>>>(
        x_hi, x_lo, w_hi + OFF_W, w_lo + OFF_W, nullptr, bias, s,
        nullptr, nullptr, Tx);

    for (int a = 0; a < 2; a++) {
        const __nv_bfloat16* wq_hi = w_hi + OFF_QKV + a * 49152;
        const __nv_bfloat16* wq_lo = w_lo + OFF_QKV + a * 49152;
        const __nv_bfloat16* wo_hi = w_hi + OFF_WO + a * 16384;
        const __nv_bfloat16* wo_lo = w_lo + OFF_WO + a * 16384;

        // z = LN1(s)
        ln_kernel<<<(T + 7) / 8, 256>>>(s, ln1_g, ln1_b, z_hi, z_lo, T);
        // imv32 = 0.25 * (q.k per head) * v   (fused qkv GEMM + rsa)
        qkv_rsa_kernel<<<tokBlocks, 256, SM_QKV>>>(
            z_hi, z_lo, wq_hi, wq_lo, imv32, T);
        // causal cumsum -> imv planes (overwrites z storage)
        cumsum_kernel<<<AA, 128>>>(imv32, imv_hi, imv_lo);
        // s += imv @ Wo^T
        mma_gemm_res<1,0,0,0><<<tokBlocks, 256, SM_RES>>>(
            imv_hi, imv_lo, wo_hi, wo_lo, nullptr, s, s, nullptr, nullptr, T);
        // z = LN2(s)
        ln_kernel<<<(T + 7) / 8, 256>>>(s, ln2_g, ln2_b, z_hi, z_lo, T);
        // h = gelu(z @ fc1^T + b1) -> planes (N=512, 4 chunks in-CTA)
        mma_gemm_res<4,0,1,1><<<tokBlocks, 256, SM_RES>>>(
            z_hi, z_lo, w_hi + OFF_FC1, w_lo + OFF_FC1, fc1_b, nullptr,
            nullptr, h_hi, h_lo, T);
        // s = h @ fc2^T + b2 + s  (K=512, streaming)
        mma_gemm_stream<<<tokBlocks, 256, SM_STREAM>>>(
            h_hi, h_lo, w_hi + OFF_FC2, w_lo + OFF_FC2, fc2_b, s, s, T, 512);
    }
    (void)in_sizes; (void)n_in; (void)out_size;
}